// round 3
// baseline (speedup 1.0000x reference)
#include <cuda_runtime.h>
#include <cuda_bf16.h>
#include <math.h>
#include <stdint.h>

#define N_NODES 50000
#define E_EDGES 800000
#define DIN 256
#define DH 128
#define DOUT 64

// ---------------- scratch (static device globals; no allocation) ----------------
__device__ __nv_bfloat16 g_h[(size_t)N_NODES * DH];   // pre-aggregation features (bf16)
__device__ __nv_bfloat16 g_a[(size_t)N_NODES * DH];   // post-layer activations (bf16)
__device__ float g_dinv[N_NODES];
__device__ int   g_deg[N_NODES];
__device__ int   g_offs[N_NODES + 1];
__device__ int   g_cursor[N_NODES];
__device__ int2  g_edge[E_EDGES];               // .x = src, .y = float bits of norm
__device__ int   g_bsum[64];
__device__ int   g_bbase[64];

// ---------------- CSR construction ----------------
__global__ void k_count(const int* __restrict__ dst, int E) {
    int i = blockIdx.x * blockDim.x + threadIdx.x;
    if (i < E) atomicAdd(&g_deg[dst[i]], 1);
}

// scan level 1: each block scans 1024 elements (256 thr x 4); also computes dinv
__global__ void k_scan1(int n) {
    __shared__ int wsum[8];
    const int t = threadIdx.x;
    const int lane = t & 31, w = t >> 5;
    const int base = blockIdx.x * 1024 + t * 4;

    int d0 = (base + 0 < n) ? g_deg[base + 0] : 0;
    int d1 = (base + 1 < n) ? g_deg[base + 1] : 0;
    int d2 = (base + 2 < n) ? g_deg[base + 2] : 0;
    int d3 = (base + 3 < n) ? g_deg[base + 3] : 0;
    if (base + 0 < n) g_dinv[base + 0] = rsqrtf((float)d0 + 1.0f);
    if (base + 1 < n) g_dinv[base + 1] = rsqrtf((float)d1 + 1.0f);
    if (base + 2 < n) g_dinv[base + 2] = rsqrtf((float)d2 + 1.0f);
    if (base + 3 < n) g_dinv[base + 3] = rsqrtf((float)d3 + 1.0f);

    int s0 = d0, s1 = s0 + d1, s2 = s1 + d2, s3 = s2 + d3;
    int ws = s3;
#pragma unroll
    for (int off = 1; off < 32; off <<= 1) {
        int v = __shfl_up_sync(0xFFFFFFFFu, ws, off);
        if (lane >= off) ws += v;
    }
    if (lane == 31) wsum[w] = ws;
    __syncthreads();
    if (w == 0 && lane < 8) {
        int v = wsum[lane];
#pragma unroll
        for (int off = 1; off < 8; off <<= 1) {
            int u = __shfl_up_sync(0x000000FFu, v, off);
            if (lane >= off) v += u;
        }
        wsum[lane] = v;
    }
    __syncthreads();
    int wbase = (w == 0) ? 0 : wsum[w - 1];
    int tbase = wbase + ws - s3;
    if (base + 0 < n) g_offs[base + 0] = tbase;
    if (base + 1 < n) g_offs[base + 1] = tbase + s0;
    if (base + 2 < n) g_offs[base + 2] = tbase + s1;
    if (base + 3 < n) g_offs[base + 3] = tbase + s2;
    if (t == 255) g_bsum[blockIdx.x] = wsum[7];
}

__global__ void k_scan2(int nb, int n) {
    __shared__ int sh[2];
    const int t = threadIdx.x;
    const int lane = t & 31, w = t >> 5;
    int v = (t < nb) ? g_bsum[t] : 0;
    int x = v;
#pragma unroll
    for (int off = 1; off < 32; off <<= 1) {
        int u = __shfl_up_sync(0xFFFFFFFFu, x, off);
        if (lane >= off) x += u;
    }
    if (lane == 31) sh[w] = x;
    __syncthreads();
    int incl = x + ((w == 1) ? sh[0] : 0);
    if (t < nb) g_bbase[t] = incl - v;
    if (t == nb - 1) g_offs[n] = incl;
}

__global__ void k_scan3(int n) {
    const int b = g_bbase[blockIdx.x];
    const int i = blockIdx.x * 1024 + threadIdx.x * 4;
#pragma unroll
    for (int q = 0; q < 4; q++) {
        if (i + q < n) {
            int o = g_offs[i + q] + b;
            g_offs[i + q] = o;
            g_cursor[i + q] = o;
        }
    }
}

__global__ void k_fill(const int* __restrict__ src, const int* __restrict__ dst, int E) {
    int i = blockIdx.x * blockDim.x + threadIdx.x;
    if (i < E) {
        int d = dst[i];
        int s = src[i];
        int pos = atomicAdd(&g_cursor[d], 1);
        g_edge[pos] = make_int2(s, __float_as_int(g_dinv[s] * g_dinv[d]));
    }
}

// ---------------- bf16 tensor-core GEMM: C[n,F] = A[n,K] @ W[K,F] ----------------
__device__ __forceinline__ void mma_bf16(float c[4], const uint32_t a[4],
                                         uint32_t b0, uint32_t b1) {
    asm volatile(
        "mma.sync.aligned.m16n8k16.row.col.f32.bf16.bf16.f32 "
        "{%0,%1,%2,%3},{%4,%5,%6,%7},{%8,%9},{%0,%1,%2,%3};"
        : "+f"(c[0]), "+f"(c[1]), "+f"(c[2]), "+f"(c[3])
        : "r"(a[0]), "r"(a[1]), "r"(a[2]), "r"(a[3]), "r"(b0), "r"(b1));
}

// BM=64, BK=32, 256 threads = 8 warps (2m x 4n). Warp tile m32 x (F/4).
// AT = float (layer 1) or __nv_bfloat16 (layers 2,3).
template <int K, int F, typename AT>
__global__ void __launch_bounds__(256) k_gemm_bf16(const AT* __restrict__ A,
                                                   const float* __restrict__ Wm,
                                                   __nv_bfloat16* __restrict__ C, int n) {
    constexpr int BM = 64, BK = 32;
    constexpr int AST = 40;            // As row stride (bf16 units), conflict-free
    constexpr int WST = 40;            // Ws row stride
    constexpr int WNW = F / 4;         // warp n-width: 32 (F=128) or 16 (F=64)
    constexpr int NT = WNW / 8;        // n8 tiles per warp

    __shared__ __nv_bfloat16 As[BM * AST];
    __shared__ __nv_bfloat16 Ws[F * WST];   // transposed: Ws[n][k]

    const int tid = threadIdx.x;
    const int lane = tid & 31;
    const int wid = tid >> 5;
    const int wm = wid >> 2;
    const int wn = wid & 3;
    const int g = lane >> 2;
    const int tg = lane & 3;
    const int row0 = blockIdx.x * BM;

    float acc[2][NT][4];
#pragma unroll
    for (int i = 0; i < 2; i++)
#pragma unroll
        for (int j = 0; j < NT; j++)
#pragma unroll
            for (int q = 0; q < 4; q++) acc[i][j][q] = 0.0f;

    for (int k0 = 0; k0 < K; k0 += BK) {
        // A tile: 64 rows x 32 k bf16. Each thread: row tid/4, 8 cols at (tid%4)*8.
        {
            int r = tid >> 2;
            int c = (tid & 3) * 8;
            int gr = row0 + r;
            __nv_bfloat16 tmp[8];
            if (gr < n) {
                if constexpr (sizeof(AT) == 4) {
                    const float4* p = (const float4*)((const float*)A + (size_t)gr * K + k0 + c);
                    float4 v0 = p[0], v1 = p[1];
                    tmp[0] = __float2bfloat16(v0.x); tmp[1] = __float2bfloat16(v0.y);
                    tmp[2] = __float2bfloat16(v0.z); tmp[3] = __float2bfloat16(v0.w);
                    tmp[4] = __float2bfloat16(v1.x); tmp[5] = __float2bfloat16(v1.y);
                    tmp[6] = __float2bfloat16(v1.z); tmp[7] = __float2bfloat16(v1.w);
                } else {
                    uint4 v = *(const uint4*)((const __nv_bfloat16*)A + (size_t)gr * K + k0 + c);
                    *(uint4*)tmp = v;
                }
            } else {
#pragma unroll
                for (int q = 0; q < 8; q++) tmp[q] = __float2bfloat16(0.0f);
            }
            *(uint4*)&As[r * AST + c] = *(uint4*)tmp;
        }
        // W tile transposed: read W[k0+k][nc..nc+3] fp32, write Ws[n][k] bf16
        {
            constexpr int NF4 = F / 4;
#pragma unroll
            for (int q = 0; q < (BK * NF4) / 256; q++) {
                int idx = tid + q * 256;
                int k = idx / NF4;
                int c4 = idx % NF4;
                float4 v = *(const float4*)(Wm + (size_t)(k0 + k) * F + c4 * 4);
                Ws[(c4 * 4 + 0) * WST + k] = __float2bfloat16(v.x);
                Ws[(c4 * 4 + 1) * WST + k] = __float2bfloat16(v.y);
                Ws[(c4 * 4 + 2) * WST + k] = __float2bfloat16(v.z);
                Ws[(c4 * 4 + 3) * WST + k] = __float2bfloat16(v.w);
            }
        }
        __syncthreads();

#pragma unroll
        for (int kk = 0; kk < BK; kk += 16) {
            uint32_t af[2][4];
#pragma unroll
            for (int i = 0; i < 2; i++) {
                int mb = wm * 32 + i * 16;
                af[i][0] = *(const uint32_t*)&As[(mb + g) * AST + kk + 2 * tg];
                af[i][1] = *(const uint32_t*)&As[(mb + g + 8) * AST + kk + 2 * tg];
                af[i][2] = *(const uint32_t*)&As[(mb + g) * AST + kk + 2 * tg + 8];
                af[i][3] = *(const uint32_t*)&As[(mb + g + 8) * AST + kk + 2 * tg + 8];
            }
#pragma unroll
            for (int j = 0; j < NT; j++) {
                int nb = wn * WNW + j * 8;
                uint32_t b0 = *(const uint32_t*)&Ws[(nb + g) * WST + kk + 2 * tg];
                uint32_t b1 = *(const uint32_t*)&Ws[(nb + g) * WST + kk + 2 * tg + 8];
#pragma unroll
                for (int i = 0; i < 2; i++) mma_bf16(acc[i][j], af[i], b0, b1);
            }
        }
        __syncthreads();
    }

    // epilogue: pack fp32 pairs -> bf16x2 stores
#pragma unroll
    for (int i = 0; i < 2; i++) {
        int gr0 = row0 + wm * 32 + i * 16 + g;
#pragma unroll
        for (int j = 0; j < NT; j++) {
            int col = wn * WNW + j * 8 + 2 * tg;
            if (gr0 < n) {
                __nv_bfloat162 p = __floats2bfloat162_rn(acc[i][j][0], acc[i][j][1]);
                *(__nv_bfloat162*)(C + (size_t)gr0 * F + col) = p;
            }
            if (gr0 + 8 < n) {
                __nv_bfloat162 p = __floats2bfloat162_rn(acc[i][j][2], acc[i][j][3]);
                *(__nv_bfloat162*)(C + (size_t)(gr0 + 8) * F + col) = p;
            }
        }
    }
}

// ---------------- aggregation: one warp per node, bf16 gather, fp32 accum ----------------
__device__ __forceinline__ void fma_bf16x4(float4& acc, uint2 v, float nm) {
    float2 lo = __bfloat1622float2(*(const __nv_bfloat162*)&v.x);
    float2 hi = __bfloat1622float2(*(const __nv_bfloat162*)&v.y);
    acc.x = fmaf(lo.x, nm, acc.x);
    acc.y = fmaf(lo.y, nm, acc.y);
    acc.z = fmaf(hi.x, nm, acc.z);
    acc.w = fmaf(hi.y, nm, acc.w);
}

// F=128: out = relu(agg + b), bf16 in / bf16 out
__global__ void k_agg128(const __nv_bfloat16* __restrict__ h, const float* __restrict__ b,
                         __nv_bfloat16* __restrict__ out, int n) {
    int gw = (blockIdx.x * blockDim.x + threadIdx.x) >> 5;
    int lane = threadIdx.x & 31;
    if (gw >= n) return;

    float4 acc = make_float4(0.f, 0.f, 0.f, 0.f);
    const int beg = g_offs[gw];
    const int end = g_offs[gw + 1];

    int e = beg;
    // 2-edge pipeline for MLP
    for (; e + 1 < end; e += 2) {
        int2 e0 = g_edge[e];
        int2 e1 = g_edge[e + 1];
        uint2 v0 = *(const uint2*)(h + (size_t)e0.x * 128 + lane * 4);
        uint2 v1 = *(const uint2*)(h + (size_t)e1.x * 128 + lane * 4);
        fma_bf16x4(acc, v0, __int_as_float(e0.y));
        fma_bf16x4(acc, v1, __int_as_float(e1.y));
    }
    if (e < end) {
        int2 e0 = g_edge[e];
        uint2 v0 = *(const uint2*)(h + (size_t)e0.x * 128 + lane * 4);
        fma_bf16x4(acc, v0, __int_as_float(e0.y));
    }
    {
        float di = g_dinv[gw];
        uint2 v = *(const uint2*)(h + (size_t)gw * 128 + lane * 4);
        fma_bf16x4(acc, v, di * di);
    }
    float4 bv = *(const float4*)(b + lane * 4);
    acc.x = fmaxf(acc.x + bv.x, 0.f);
    acc.y = fmaxf(acc.y + bv.y, 0.f);
    acc.z = fmaxf(acc.z + bv.z, 0.f);
    acc.w = fmaxf(acc.w + bv.w, 0.f);
    uint2 o;
    *(__nv_bfloat162*)&o.x = __floats2bfloat162_rn(acc.x, acc.y);
    *(__nv_bfloat162*)&o.y = __floats2bfloat162_rn(acc.z, acc.w);
    *(uint2*)(out + (size_t)gw * 128 + lane * 4) = o;
}

// F=64 with fused log_softmax, bf16 in / fp32 out
__global__ void k_agg64_lsm(const __nv_bfloat16* __restrict__ h, const float* __restrict__ b,
                            float* __restrict__ out, int n) {
    int gw = (blockIdx.x * blockDim.x + threadIdx.x) >> 5;
    int lane = threadIdx.x & 31;
    if (gw >= n) return;

    float2 acc = make_float2(0.f, 0.f);
    const int beg = g_offs[gw];
    const int end = g_offs[gw + 1];

    int e = beg;
    for (; e + 1 < end; e += 2) {
        int2 e0 = g_edge[e];
        int2 e1 = g_edge[e + 1];
        uint32_t v0 = *(const uint32_t*)(h + (size_t)e0.x * 64 + lane * 2);
        uint32_t v1 = *(const uint32_t*)(h + (size_t)e1.x * 64 + lane * 2);
        float2 f0 = __bfloat1622float2(*(const __nv_bfloat162*)&v0);
        float2 f1 = __bfloat1622float2(*(const __nv_bfloat162*)&v1);
        float n0 = __int_as_float(e0.y), n1 = __int_as_float(e1.y);
        acc.x = fmaf(f0.x, n0, acc.x); acc.y = fmaf(f0.y, n0, acc.y);
        acc.x = fmaf(f1.x, n1, acc.x); acc.y = fmaf(f1.y, n1, acc.y);
    }
    if (e < end) {
        int2 e0 = g_edge[e];
        uint32_t v0 = *(const uint32_t*)(h + (size_t)e0.x * 64 + lane * 2);
        float2 f0 = __bfloat1622float2(*(const __nv_bfloat162*)&v0);
        float n0 = __int_as_float(e0.y);
        acc.x = fmaf(f0.x, n0, acc.x); acc.y = fmaf(f0.y, n0, acc.y);
    }
    {
        float di = g_dinv[gw];
        float sw = di * di;
        uint32_t v = *(const uint32_t*)(h + (size_t)gw * 64 + lane * 2);
        float2 f = __bfloat1622float2(*(const __nv_bfloat162*)&v);
        acc.x = fmaf(f.x, sw, acc.x); acc.y = fmaf(f.y, sw, acc.y);
    }
    float2 bv = *(const float2*)(b + lane * 2);
    acc.x += bv.x;
    acc.y += bv.y;

    float m = fmaxf(acc.x, acc.y);
#pragma unroll
    for (int o = 16; o > 0; o >>= 1) m = fmaxf(m, __shfl_xor_sync(0xFFFFFFFFu, m, o));
    float se = expf(acc.x - m) + expf(acc.y - m);
#pragma unroll
    for (int o = 16; o > 0; o >>= 1) se += __shfl_xor_sync(0xFFFFFFFFu, se, o);
    float ls = m + logf(se);
    *(float2*)(out + (size_t)gw * 64 + lane * 2) = make_float2(acc.x - ls, acc.y - ls);
}

// ---------------- launch ----------------
extern "C" void kernel_launch(void* const* d_in, const int* in_sizes, int n_in,
                              void* d_out, int out_size) {
    const float* x  = (const float*)d_in[0];
    const int* ei   = (const int*)d_in[1];
    const float* W0 = (const float*)d_in[2];
    const float* b0 = (const float*)d_in[3];
    const float* W1 = (const float*)d_in[4];
    const float* b1 = (const float*)d_in[5];
    const float* W2 = (const float*)d_in[6];
    const float* b2 = (const float*)d_in[7];
    float* out = (float*)d_out;

    const int N = in_sizes[0] / DIN;
    const int E = in_sizes[1] / 2;
    const int* src = ei;
    const int* dst = ei + E;

    __nv_bfloat16 *h_ptr = nullptr, *a_ptr = nullptr;
    int* deg_ptr = nullptr;
    cudaGetSymbolAddress((void**)&h_ptr, g_h);
    cudaGetSymbolAddress((void**)&a_ptr, g_a);
    cudaGetSymbolAddress((void**)&deg_ptr, g_deg);

    const int TB = 256;
    const int nb = (N + 1023) / 1024;

    // CSR build
    cudaMemsetAsync(deg_ptr, 0, (size_t)N * sizeof(int));
    k_count<<<(E + TB - 1) / TB, TB>>>(dst, E);
    k_scan1<<<nb, 256>>>(N);
    k_scan2<<<1, 64>>>(nb, N);
    k_scan3<<<nb, 256>>>(N);
    k_fill <<<(E + TB - 1) / TB, TB>>>(src, dst, E);

    const int gemm_grid = (N + 63) / 64;
    const int agg_grid = (N * 32 + TB - 1) / TB;

    // layer 1
    k_gemm_bf16<DIN, DH, float><<<gemm_grid, 256>>>(x, W0, h_ptr, N);
    k_agg128<<<agg_grid, TB>>>(h_ptr, b0, a_ptr, N);

    // layer 2
    k_gemm_bf16<DH, DH, __nv_bfloat16><<<gemm_grid, 256>>>(a_ptr, W1, h_ptr, N);
    k_agg128<<<agg_grid, TB>>>(h_ptr, b1, a_ptr, N);

    // layer 3 + fused log_softmax
    k_gemm_bf16<DH, DOUT, __nv_bfloat16><<<gemm_grid, 256>>>(a_ptr, W2, h_ptr, N);
    k_agg64_lsm<<<agg_grid, TB>>>(h_ptr, b2, out, N);
}

// round 4
// speedup vs baseline: 1.1913x; 1.1913x over previous
#include <cuda_runtime.h>
#include <cuda_bf16.h>
#include <math.h>
#include <stdint.h>

#define N_NODES 50000
#define E_EDGES 800000
#define DIN 256
#define DH 128
#define DOUT 64

// ---------------- scratch (static device globals; no allocation) ----------------
__device__ __nv_bfloat16 g_h[(size_t)N_NODES * DH];   // GEMM out / agg gather in (bf16)
__device__ float g_a[(size_t)N_NODES * DH];           // agg out / GEMM in (fp32)
__device__ float g_dinv[N_NODES];
__device__ int   g_deg[N_NODES];
__device__ int   g_offs[N_NODES + 1];
__device__ int   g_cursor[N_NODES];
__device__ int2  g_edge[E_EDGES];               // .x = src, .y = float bits of norm
__device__ unsigned long long g_state[64];      // decoupled-lookback state

// ---------------- CSR construction ----------------
__global__ void k_count(const int* __restrict__ dst, int E) {
    int i = blockIdx.x * blockDim.x + threadIdx.x;
    if (i < E) atomicAdd(&g_deg[dst[i]], 1);
}

// Single-pass scan over g_deg with decoupled lookback (49 blocks, all resident).
// Also computes g_dinv, initializes g_cursor = g_offs, writes g_offs[n].
__global__ void k_scan_all(int n, int nb) {
    __shared__ int wsum[8];
    __shared__ int s_base;
    const int t = threadIdx.x;
    const int lane = t & 31, w = t >> 5;
    const int base = blockIdx.x * 1024 + t * 4;

    int d0 = (base + 0 < n) ? g_deg[base + 0] : 0;
    int d1 = (base + 1 < n) ? g_deg[base + 1] : 0;
    int d2 = (base + 2 < n) ? g_deg[base + 2] : 0;
    int d3 = (base + 3 < n) ? g_deg[base + 3] : 0;
    if (base + 0 < n) g_dinv[base + 0] = rsqrtf((float)d0 + 1.0f);
    if (base + 1 < n) g_dinv[base + 1] = rsqrtf((float)d1 + 1.0f);
    if (base + 2 < n) g_dinv[base + 2] = rsqrtf((float)d2 + 1.0f);
    if (base + 3 < n) g_dinv[base + 3] = rsqrtf((float)d3 + 1.0f);

    int s0 = d0, s1 = s0 + d1, s2 = s1 + d2, s3 = s2 + d3;
    int ws = s3;
#pragma unroll
    for (int off = 1; off < 32; off <<= 1) {
        int v = __shfl_up_sync(0xFFFFFFFFu, ws, off);
        if (lane >= off) ws += v;
    }
    if (lane == 31) wsum[w] = ws;
    __syncthreads();
    if (w == 0 && lane < 8) {
        int v = wsum[lane];
#pragma unroll
        for (int off = 1; off < 8; off <<= 1) {
            int u = __shfl_up_sync(0x000000FFu, v, off);
            if (lane >= off) v += u;
        }
        wsum[lane] = v;
    }
    __syncthreads();

    // publish this block's aggregate (payload rides with the atomic)
    if (t == 0) {
        unsigned long long pkt = (((unsigned long long)(unsigned)wsum[7]) << 2) | 1ull;
        atomicExch(&g_state[blockIdx.x], pkt);
    }

    // warp 0: parallel lookback over all predecessors' aggregates
    if (w == 0) {
        int sum = 0;
        volatile unsigned long long* st = (volatile unsigned long long*)g_state;
        for (int p0 = (int)blockIdx.x - 1; p0 >= 0; p0 -= 32) {
            int idx = p0 - lane;
            if (idx >= 0) {
                unsigned long long v;
                do { v = st[idx]; } while ((v & 3ull) == 0ull);
                sum += (int)(v >> 2);
            }
        }
#pragma unroll
        for (int off = 16; off > 0; off >>= 1)
            sum += __shfl_xor_sync(0xFFFFFFFFu, sum, off);
        if (lane == 0) s_base = sum;
    }
    __syncthreads();

    const int blk = s_base;
    int wbase = (w == 0) ? 0 : wsum[w - 1];
    int tbase = blk + wbase + ws - s3;
    if (base + 0 < n) { g_offs[base + 0] = tbase;      g_cursor[base + 0] = tbase; }
    if (base + 1 < n) { g_offs[base + 1] = tbase + s0; g_cursor[base + 1] = tbase + s0; }
    if (base + 2 < n) { g_offs[base + 2] = tbase + s1; g_cursor[base + 2] = tbase + s1; }
    if (base + 3 < n) { g_offs[base + 3] = tbase + s2; g_cursor[base + 3] = tbase + s2; }
    if (blockIdx.x == (unsigned)(nb - 1) && t == 255) g_offs[n] = blk + wsum[7];
}

__global__ void k_fill(const int* __restrict__ src, const int* __restrict__ dst, int E) {
    int i = blockIdx.x * blockDim.x + threadIdx.x;
    if (i < E) {
        int d = dst[i];
        int s = src[i];
        int pos = atomicAdd(&g_cursor[d], 1);
        g_edge[pos] = make_int2(s, __float_as_int(g_dinv[s] * g_dinv[d]));
    }
}

// ---------------- TF32 tensor-core GEMM: C[n,F](bf16) = A[n,K](f32) @ W[K,F](f32) ----
__device__ __forceinline__ float f2tf32(float x) {
    uint32_t r;
    asm("cvt.rna.tf32.f32 %0, %1;" : "=r"(r) : "f"(x));
    return __uint_as_float(r);
}

__device__ __forceinline__ void mma_tf32(float c[4], const uint32_t a[4],
                                         uint32_t b0, uint32_t b1) {
    asm volatile(
        "mma.sync.aligned.m16n8k8.row.col.f32.tf32.tf32.f32 "
        "{%0,%1,%2,%3},{%4,%5,%6,%7},{%8,%9},{%0,%1,%2,%3};"
        : "+f"(c[0]), "+f"(c[1]), "+f"(c[2]), "+f"(c[3])
        : "r"(a[0]), "r"(a[1]), "r"(a[2]), "r"(a[3]), "r"(b0), "r"(b1));
}

// BM=64, BK=32, 256 threads = 8 warps (2m x 4n). Warp tile m32 x (F/4).
template <int K, int F>
__global__ void __launch_bounds__(256) k_gemm_tf32(const float* __restrict__ A,
                                                   const float* __restrict__ Wm,
                                                   __nv_bfloat16* __restrict__ C, int n) {
    constexpr int BM = 64, BK = 32;
    constexpr int AROW = 36;
    constexpr int WROW = F + 4;
    constexpr int WNW = F / 4;
    constexpr int NT = WNW / 8;

    __shared__ float As[BM * AROW];
    __shared__ float Ws[BK * WROW];

    const int tid = threadIdx.x;
    const int lane = tid & 31;
    const int wid = tid >> 5;
    const int wm = wid >> 2;
    const int wn = wid & 3;
    const int g = lane >> 2;
    const int tg = lane & 3;
    const int row0 = blockIdx.x * BM;

    float acc[2][NT][4];
#pragma unroll
    for (int i = 0; i < 2; i++)
#pragma unroll
        for (int j = 0; j < NT; j++)
#pragma unroll
            for (int q = 0; q < 4; q++) acc[i][j][q] = 0.0f;

    for (int k0 = 0; k0 < K; k0 += BK) {
#pragma unroll
        for (int q = 0; q < 2; q++) {
            int idx4 = tid * 2 + q;
            int r = idx4 >> 3, c4 = idx4 & 7;
            int gr = row0 + r;
            float4 v = make_float4(0.f, 0.f, 0.f, 0.f);
            if (gr < n) v = *(const float4*)(A + (size_t)gr * K + k0 + c4 * 4);
            float4 tt = make_float4(f2tf32(v.x), f2tf32(v.y), f2tf32(v.z), f2tf32(v.w));
            *(float4*)&As[r * AROW + c4 * 4] = tt;
        }
#pragma unroll
        for (int q = 0; q < (BK * F / 4) / 256; q++) {
            int idx4 = tid + q * 256;
            int r = idx4 / (F / 4), c4 = idx4 % (F / 4);
            float4 v = *(const float4*)(Wm + (size_t)(k0 + r) * F + c4 * 4);
            float4 tt = make_float4(f2tf32(v.x), f2tf32(v.y), f2tf32(v.z), f2tf32(v.w));
            *(float4*)&Ws[r * WROW + c4 * 4] = tt;
        }
        __syncthreads();

#pragma unroll
        for (int kk = 0; kk < BK; kk += 8) {
            uint32_t af[2][4];
#pragma unroll
            for (int i = 0; i < 2; i++) {
                int mb = wm * 32 + i * 16;
                af[i][0] = __float_as_uint(As[(mb + g) * AROW + kk + tg]);
                af[i][1] = __float_as_uint(As[(mb + g + 8) * AROW + kk + tg]);
                af[i][2] = __float_as_uint(As[(mb + g) * AROW + kk + tg + 4]);
                af[i][3] = __float_as_uint(As[(mb + g + 8) * AROW + kk + tg + 4]);
            }
#pragma unroll
            for (int j = 0; j < NT; j++) {
                int nb2 = wn * WNW + j * 8;
                uint32_t b0 = __float_as_uint(Ws[(kk + tg) * WROW + nb2 + g]);
                uint32_t b1 = __float_as_uint(Ws[(kk + tg + 4) * WROW + nb2 + g]);
#pragma unroll
                for (int i = 0; i < 2; i++) mma_tf32(acc[i][j], af[i], b0, b1);
            }
        }
        __syncthreads();
    }

    // epilogue: bf16x2 stores
#pragma unroll
    for (int i = 0; i < 2; i++) {
        int gr0 = row0 + wm * 32 + i * 16 + g;
#pragma unroll
        for (int j = 0; j < NT; j++) {
            int col = wn * WNW + j * 8 + 2 * tg;
            if (gr0 < n)
                *(__nv_bfloat162*)(C + (size_t)gr0 * F + col) =
                    __floats2bfloat162_rn(acc[i][j][0], acc[i][j][1]);
            if (gr0 + 8 < n)
                *(__nv_bfloat162*)(C + (size_t)(gr0 + 8) * F + col) =
                    __floats2bfloat162_rn(acc[i][j][2], acc[i][j][3]);
        }
    }
}

// ---------------- aggregation: one warp per node, bf16 gather, fp32 accum ----------------
__device__ __forceinline__ void fma_bf16x4(float4& acc, uint2 v, float nm) {
    float2 lo = __bfloat1622float2(*(const __nv_bfloat162*)&v.x);
    float2 hi = __bfloat1622float2(*(const __nv_bfloat162*)&v.y);
    acc.x = fmaf(lo.x, nm, acc.x);
    acc.y = fmaf(lo.y, nm, acc.y);
    acc.z = fmaf(hi.x, nm, acc.z);
    acc.w = fmaf(hi.y, nm, acc.w);
}

// F=128: out(f32) = relu(agg + b), gather h (bf16)
__global__ void k_agg128(const __nv_bfloat16* __restrict__ h, const float* __restrict__ b,
                         float* __restrict__ out, int n) {
    int gw = (blockIdx.x * blockDim.x + threadIdx.x) >> 5;
    int lane = threadIdx.x & 31;
    if (gw >= n) return;

    float4 acc = make_float4(0.f, 0.f, 0.f, 0.f);
    const int beg = g_offs[gw];
    const int end = g_offs[gw + 1];

    int e = beg;
    for (; e + 1 < end; e += 2) {
        int2 e0 = g_edge[e];
        int2 e1 = g_edge[e + 1];
        uint2 v0 = *(const uint2*)(h + (size_t)e0.x * 128 + lane * 4);
        uint2 v1 = *(const uint2*)(h + (size_t)e1.x * 128 + lane * 4);
        fma_bf16x4(acc, v0, __int_as_float(e0.y));
        fma_bf16x4(acc, v1, __int_as_float(e1.y));
    }
    if (e < end) {
        int2 e0 = g_edge[e];
        uint2 v0 = *(const uint2*)(h + (size_t)e0.x * 128 + lane * 4);
        fma_bf16x4(acc, v0, __int_as_float(e0.y));
    }
    {
        float di = g_dinv[gw];
        uint2 v = *(const uint2*)(h + (size_t)gw * 128 + lane * 4);
        fma_bf16x4(acc, v, di * di);
    }
    float4 bv = *(const float4*)(b + lane * 4);
    acc.x = fmaxf(acc.x + bv.x, 0.f);
    acc.y = fmaxf(acc.y + bv.y, 0.f);
    acc.z = fmaxf(acc.z + bv.z, 0.f);
    acc.w = fmaxf(acc.w + bv.w, 0.f);
    *(float4*)(out + (size_t)gw * 128 + lane * 4) = acc;
}

// F=64 with fused log_softmax, bf16 gather in / fp32 out
__global__ void k_agg64_lsm(const __nv_bfloat16* __restrict__ h, const float* __restrict__ b,
                            float* __restrict__ out, int n) {
    int gw = (blockIdx.x * blockDim.x + threadIdx.x) >> 5;
    int lane = threadIdx.x & 31;
    if (gw >= n) return;

    float2 acc = make_float2(0.f, 0.f);
    const int beg = g_offs[gw];
    const int end = g_offs[gw + 1];

    int e = beg;
    for (; e + 1 < end; e += 2) {
        int2 e0 = g_edge[e];
        int2 e1 = g_edge[e + 1];
        uint32_t v0 = *(const uint32_t*)(h + (size_t)e0.x * 64 + lane * 2);
        uint32_t v1 = *(const uint32_t*)(h + (size_t)e1.x * 64 + lane * 2);
        float2 f0 = __bfloat1622float2(*(const __nv_bfloat162*)&v0);
        float2 f1 = __bfloat1622float2(*(const __nv_bfloat162*)&v1);
        float n0 = __int_as_float(e0.y), n1 = __int_as_float(e1.y);
        acc.x = fmaf(f0.x, n0, acc.x); acc.y = fmaf(f0.y, n0, acc.y);
        acc.x = fmaf(f1.x, n1, acc.x); acc.y = fmaf(f1.y, n1, acc.y);
    }
    if (e < end) {
        int2 e0 = g_edge[e];
        uint32_t v0 = *(const uint32_t*)(h + (size_t)e0.x * 64 + lane * 2);
        float2 f0 = __bfloat1622float2(*(const __nv_bfloat162*)&v0);
        float n0 = __int_as_float(e0.y);
        acc.x = fmaf(f0.x, n0, acc.x); acc.y = fmaf(f0.y, n0, acc.y);
    }
    {
        float di = g_dinv[gw];
        float sw = di * di;
        uint32_t v = *(const uint32_t*)(h + (size_t)gw * 64 + lane * 2);
        float2 f = __bfloat1622float2(*(const __nv_bfloat162*)&v);
        acc.x = fmaf(f.x, sw, acc.x); acc.y = fmaf(f.y, sw, acc.y);
    }
    float2 bv = *(const float2*)(b + lane * 2);
    acc.x += bv.x;
    acc.y += bv.y;

    float m = fmaxf(acc.x, acc.y);
#pragma unroll
    for (int o = 16; o > 0; o >>= 1) m = fmaxf(m, __shfl_xor_sync(0xFFFFFFFFu, m, o));
    float se = expf(acc.x - m) + expf(acc.y - m);
#pragma unroll
    for (int o = 16; o > 0; o >>= 1) se += __shfl_xor_sync(0xFFFFFFFFu, se, o);
    float ls = m + logf(se);
    *(float2*)(out + (size_t)gw * 64 + lane * 2) = make_float2(acc.x - ls, acc.y - ls);
}

// ---------------- launch ----------------
extern "C" void kernel_launch(void* const* d_in, const int* in_sizes, int n_in,
                              void* d_out, int out_size) {
    const float* x  = (const float*)d_in[0];
    const int* ei   = (const int*)d_in[1];
    const float* W0 = (const float*)d_in[2];
    const float* b0 = (const float*)d_in[3];
    const float* W1 = (const float*)d_in[4];
    const float* b1 = (const float*)d_in[5];
    const float* W2 = (const float*)d_in[6];
    const float* b2 = (const float*)d_in[7];
    float* out = (float*)d_out;

    const int N = in_sizes[0] / DIN;
    const int E = in_sizes[1] / 2;
    const int* src = ei;
    const int* dst = ei + E;

    __nv_bfloat16* h_ptr = nullptr;
    float* a_ptr = nullptr;
    int* deg_ptr = nullptr;
    void* st_ptr = nullptr;
    cudaGetSymbolAddress((void**)&h_ptr, g_h);
    cudaGetSymbolAddress((void**)&a_ptr, g_a);
    cudaGetSymbolAddress((void**)&deg_ptr, g_deg);
    cudaGetSymbolAddress(&st_ptr, g_state);

    const int TB = 256;
    const int nb = (N + 1023) / 1024;

    // CSR build
    cudaMemsetAsync(deg_ptr, 0, (size_t)N * sizeof(int));
    cudaMemsetAsync(st_ptr, 0, 64 * sizeof(unsigned long long));
    k_count<<<(E + TB - 1) / TB, TB>>>(dst, E);
    k_scan_all<<<nb, 256>>>(N, nb);
    k_fill<<<(E + TB - 1) / TB, TB>>>(src, dst, E);

    const int gemm_grid = (N + 63) / 64;
    const int agg_grid = (N * 32 + TB - 1) / TB;

    // layer 1: x fp32 -> h bf16 ; agg -> a fp32
    k_gemm_tf32<DIN, DH><<<gemm_grid, 256>>>(x, W0, h_ptr, N);
    k_agg128<<<agg_grid, TB>>>(h_ptr, b0, a_ptr, N);

    // layer 2
    k_gemm_tf32<DH, DH><<<gemm_grid, 256>>>(a_ptr, W1, h_ptr, N);
    k_agg128<<<agg_grid, TB>>>(h_ptr, b1, a_ptr, N);

    // layer 3 + fused log_softmax
    k_gemm_tf32<DH, DOUT><<<gemm_grid, 256>>>(a_ptr, W2, h_ptr, N);
    k_agg64_lsm<<<agg_grid, TB>>>(h_ptr, b2, out, N);
}

// round 5
// speedup vs baseline: 1.4642x; 1.2291x over previous
#include <cuda_runtime.h>
#include <cuda_bf16.h>
#include <math.h>
#include <stdint.h>

#define N_NODES 50000
#define E_EDGES 800000
#define DIN 256
#define DH 128
#define DOUT 64

// ---------------- scratch (static device globals; no allocation) ----------------
__device__ __nv_bfloat16 g_h[(size_t)N_NODES * DH];   // GEMM out / agg gather in (bf16)
__device__ __nv_bfloat16 g_a[(size_t)N_NODES * DH];   // agg out / GEMM in (bf16)
__device__ float g_dinv[N_NODES];
__device__ int   g_deg[N_NODES];
__device__ int   g_offs[N_NODES + 1];
__device__ int   g_cursor[N_NODES];
__device__ int2  g_edge[E_EDGES];               // .x = src, .y = float bits of norm
__device__ unsigned long long g_state[64];      // decoupled-lookback state

// ---------------- CSR construction ----------------
__global__ void k_count(const int* __restrict__ dst, int E) {
    int i = blockIdx.x * blockDim.x + threadIdx.x;
    if (i < E) atomicAdd(&g_deg[dst[i]], 1);
}

// Single-pass scan + dinv + cursor init (decoupled lookback, 49 blocks)
__global__ void k_scan_all(int n, int nb) {
    __shared__ int wsum[8];
    __shared__ int s_base;
    const int t = threadIdx.x;
    const int lane = t & 31, w = t >> 5;
    const int base = blockIdx.x * 1024 + t * 4;

    int d0 = (base + 0 < n) ? g_deg[base + 0] : 0;
    int d1 = (base + 1 < n) ? g_deg[base + 1] : 0;
    int d2 = (base + 2 < n) ? g_deg[base + 2] : 0;
    int d3 = (base + 3 < n) ? g_deg[base + 3] : 0;
    if (base + 0 < n) g_dinv[base + 0] = rsqrtf((float)d0 + 1.0f);
    if (base + 1 < n) g_dinv[base + 1] = rsqrtf((float)d1 + 1.0f);
    if (base + 2 < n) g_dinv[base + 2] = rsqrtf((float)d2 + 1.0f);
    if (base + 3 < n) g_dinv[base + 3] = rsqrtf((float)d3 + 1.0f);

    int s0 = d0, s1 = s0 + d1, s2 = s1 + d2, s3 = s2 + d3;
    int ws = s3;
#pragma unroll
    for (int off = 1; off < 32; off <<= 1) {
        int v = __shfl_up_sync(0xFFFFFFFFu, ws, off);
        if (lane >= off) ws += v;
    }
    if (lane == 31) wsum[w] = ws;
    __syncthreads();
    if (w == 0 && lane < 8) {
        int v = wsum[lane];
#pragma unroll
        for (int off = 1; off < 8; off <<= 1) {
            int u = __shfl_up_sync(0x000000FFu, v, off);
            if (lane >= off) v += u;
        }
        wsum[lane] = v;
    }
    __syncthreads();

    if (t == 0) {
        unsigned long long pkt = (((unsigned long long)(unsigned)wsum[7]) << 2) | 1ull;
        atomicExch(&g_state[blockIdx.x], pkt);
    }
    if (w == 0) {
        int sum = 0;
        volatile unsigned long long* st = (volatile unsigned long long*)g_state;
        for (int p0 = (int)blockIdx.x - 1; p0 >= 0; p0 -= 32) {
            int idx = p0 - lane;
            if (idx >= 0) {
                unsigned long long v;
                do { v = st[idx]; } while ((v & 3ull) == 0ull);
                sum += (int)(v >> 2);
            }
        }
#pragma unroll
        for (int off = 16; off > 0; off >>= 1)
            sum += __shfl_xor_sync(0xFFFFFFFFu, sum, off);
        if (lane == 0) s_base = sum;
    }
    __syncthreads();

    const int blk = s_base;
    int wbase = (w == 0) ? 0 : wsum[w - 1];
    int tbase = blk + wbase + ws - s3;
    if (base + 0 < n) { g_offs[base + 0] = tbase;      g_cursor[base + 0] = tbase; }
    if (base + 1 < n) { g_offs[base + 1] = tbase + s0; g_cursor[base + 1] = tbase + s0; }
    if (base + 2 < n) { g_offs[base + 2] = tbase + s1; g_cursor[base + 2] = tbase + s1; }
    if (base + 3 < n) { g_offs[base + 3] = tbase + s2; g_cursor[base + 3] = tbase + s2; }
    if (blockIdx.x == (unsigned)(nb - 1) && t == 255) g_offs[n] = blk + wsum[7];
}

__global__ void k_fill(const int* __restrict__ src, const int* __restrict__ dst, int E) {
    int i = blockIdx.x * blockDim.x + threadIdx.x;
    if (i < E) {
        int d = dst[i];
        int s = src[i];
        int pos = atomicAdd(&g_cursor[d], 1);
        g_edge[pos] = make_int2(s, __float_as_int(g_dinv[s] * g_dinv[d]));
    }
}

// ---------------- bf16 tensor-core GEMM with ldmatrix ----------------
__device__ __forceinline__ uint32_t smem_u32(const void* p) {
    return (uint32_t)__cvta_generic_to_shared(p);
}

__device__ __forceinline__ void ldsm_x4(uint32_t r[4], uint32_t addr) {
    asm volatile("ldmatrix.sync.aligned.m8n8.x4.shared.b16 {%0,%1,%2,%3}, [%4];"
                 : "=r"(r[0]), "=r"(r[1]), "=r"(r[2]), "=r"(r[3]) : "r"(addr));
}

__device__ __forceinline__ void ldsm_x4_t(uint32_t r[4], uint32_t addr) {
    asm volatile("ldmatrix.sync.aligned.m8n8.x4.trans.shared.b16 {%0,%1,%2,%3}, [%4];"
                 : "=r"(r[0]), "=r"(r[1]), "=r"(r[2]), "=r"(r[3]) : "r"(addr));
}

__device__ __forceinline__ void mma_bf16(float c[4], const uint32_t a[4],
                                         uint32_t b0, uint32_t b1) {
    asm volatile(
        "mma.sync.aligned.m16n8k16.row.col.f32.bf16.bf16.f32 "
        "{%0,%1,%2,%3},{%4,%5,%6,%7},{%8,%9},{%0,%1,%2,%3};"
        : "+f"(c[0]), "+f"(c[1]), "+f"(c[2]), "+f"(c[3])
        : "r"(a[0]), "r"(a[1]), "r"(a[2]), "r"(a[3]), "r"(b0), "r"(b1));
}

// BM=64, BK=32, 256 threads = 8 warps (2m x 4n). Warp tile m32 x (F/4).
// As: [row][k] bf16 stride 40. Ws: [k][n] bf16 stride F+8 (k-major; B via ldmatrix.trans).
// AT = float (layer 1, converted while staging) or __nv_bfloat16 (layers 2,3).
template <int K, int F, typename AT>
__global__ void __launch_bounds__(256) k_gemm_bf16(const AT* __restrict__ A,
                                                   const float* __restrict__ Wm,
                                                   __nv_bfloat16* __restrict__ C, int n) {
    constexpr int BM = 64, BK = 32;
    constexpr int AST = 40;        // bf16 units; ldmatrix rows at 80B stride: conflict-free
    constexpr int WST = F + 8;     // bf16 units; rows at (F+8)*2 B: 16B offset pattern, conflict-free
    constexpr int WNW = F / 4;     // warp n-width: 32 (F=128) or 16 (F=64)
    constexpr int NT = WNW / 8;    // n8 tiles per warp: 4 or 2

    __shared__ __nv_bfloat16 As[BM * AST];
    __shared__ __nv_bfloat16 Ws[BK * WST];

    const int tid = threadIdx.x;
    const int lane = tid & 31;
    const int wid = tid >> 5;
    const int wm = wid >> 2;       // 0..1
    const int wn = wid & 3;        // 0..3
    const int quad = lane >> 3;    // 0..3
    const int lq = lane & 7;       // 0..7
    const int g = lane >> 2;       // for epilogue
    const int tg = lane & 3;
    const int row0 = blockIdx.x * BM;

    float acc[2][NT][4];
#pragma unroll
    for (int i = 0; i < 2; i++)
#pragma unroll
        for (int j = 0; j < NT; j++)
#pragma unroll
            for (int q = 0; q < 4; q++) acc[i][j][q] = 0.0f;

    // per-thread ldmatrix base offsets (element units)
    // A, tile i, k-step kk: row = wm*32 + i*16 + (quad&1)*8 + lq ; col = kk + (quad>>1)*8
    const int a_row = wm * 32 + (quad & 1) * 8 + lq;
    const int a_colq = (quad >> 1) * 8;
    // B, group j2, k-step kk: row = kk + (quad&1)*8 + lq ; col = wn*WNW + j2*16 + (quad>>1)*8
    const int b_rowq = (quad & 1) * 8 + lq;
    const int b_col = wn * WNW + (quad >> 1) * 8;

    const uint32_t as_base = smem_u32(As);
    const uint32_t ws_base = smem_u32(Ws);

    for (int k0 = 0; k0 < K; k0 += BK) {
        // ---- stage A tile: row = tid/4, 8 k's at (tid%4)*8 ----
        {
            int r = tid >> 2;
            int c = (tid & 3) * 8;
            int gr = row0 + r;
            __nv_bfloat16 tmp[8];
            if (gr < n) {
                if constexpr (sizeof(AT) == 4) {
                    const float4* p = (const float4*)((const float*)A + (size_t)gr * K + k0 + c);
                    float4 v0 = p[0], v1 = p[1];
                    tmp[0] = __float2bfloat16(v0.x); tmp[1] = __float2bfloat16(v0.y);
                    tmp[2] = __float2bfloat16(v0.z); tmp[3] = __float2bfloat16(v0.w);
                    tmp[4] = __float2bfloat16(v1.x); tmp[5] = __float2bfloat16(v1.y);
                    tmp[6] = __float2bfloat16(v1.z); tmp[7] = __float2bfloat16(v1.w);
                } else {
                    *(uint4*)tmp = *(const uint4*)((const __nv_bfloat16*)A + (size_t)gr * K + k0 + c);
                }
            } else {
#pragma unroll
                for (int q = 0; q < 8; q++) tmp[q] = __float2bfloat16(0.0f);
            }
            *(uint4*)&As[r * AST + c] = *(uint4*)tmp;
        }
        // ---- stage W tile k-major: Ws[k][n] = bf16(W[k0+k][n]) ----
        {
            constexpr int NF4 = F / 4;
#pragma unroll
            for (int q = 0; q < (BK * NF4) / 256; q++) {
                int idx = tid + q * 256;
                int k = idx / NF4;
                int c4 = idx % NF4;
                float4 v = *(const float4*)(Wm + (size_t)(k0 + k) * F + c4 * 4);
                __nv_bfloat162 p0 = __floats2bfloat162_rn(v.x, v.y);
                __nv_bfloat162 p1 = __floats2bfloat162_rn(v.z, v.w);
                *(__nv_bfloat162*)&Ws[k * WST + c4 * 4 + 0] = p0;
                *(__nv_bfloat162*)&Ws[k * WST + c4 * 4 + 2] = p1;
            }
        }
        __syncthreads();

#pragma unroll
        for (int kk = 0; kk < BK; kk += 16) {
            uint32_t af[2][4];
#pragma unroll
            for (int i = 0; i < 2; i++)
                ldsm_x4(af[i], as_base + ((a_row + i * 16) * AST + kk + a_colq) * 2);

            uint32_t bf[NT][2];
#pragma unroll
            for (int j2 = 0; j2 < NT / 2; j2++) {
                uint32_t r[4];
                ldsm_x4_t(r, ws_base + ((kk + b_rowq) * WST + b_col + j2 * 16) * 2);
                bf[2 * j2][0] = r[0]; bf[2 * j2][1] = r[1];
                bf[2 * j2 + 1][0] = r[2]; bf[2 * j2 + 1][1] = r[3];
            }
#pragma unroll
            for (int j = 0; j < NT; j++)
#pragma unroll
                for (int i = 0; i < 2; i++) mma_bf16(acc[i][j], af[i], bf[j][0], bf[j][1]);
        }
        __syncthreads();
    }

    // ---- epilogue: bf16x2 stores ----
#pragma unroll
    for (int i = 0; i < 2; i++) {
        int gr0 = row0 + wm * 32 + i * 16 + g;
#pragma unroll
        for (int j = 0; j < NT; j++) {
            int col = wn * WNW + j * 8 + 2 * tg;
            if (gr0 < n)
                *(__nv_bfloat162*)(C + (size_t)gr0 * F + col) =
                    __floats2bfloat162_rn(acc[i][j][0], acc[i][j][1]);
            if (gr0 + 8 < n)
                *(__nv_bfloat162*)(C + (size_t)(gr0 + 8) * F + col) =
                    __floats2bfloat162_rn(acc[i][j][2], acc[i][j][3]);
        }
    }
}

// ---------------- aggregation: one warp per node, bf16 gather, fp32 accum ----------------
__device__ __forceinline__ void fma_bf16x4(float4& acc, uint2 v, float nm) {
    float2 lo = __bfloat1622float2(*(const __nv_bfloat162*)&v.x);
    float2 hi = __bfloat1622float2(*(const __nv_bfloat162*)&v.y);
    acc.x = fmaf(lo.x, nm, acc.x);
    acc.y = fmaf(lo.y, nm, acc.y);
    acc.z = fmaf(hi.x, nm, acc.z);
    acc.w = fmaf(hi.y, nm, acc.w);
}

// F=128: out(bf16) = relu(agg + b), gather h (bf16)
__global__ void k_agg128(const __nv_bfloat16* __restrict__ h, const float* __restrict__ b,
                         __nv_bfloat16* __restrict__ out, int n) {
    int gw = (blockIdx.x * blockDim.x + threadIdx.x) >> 5;
    int lane = threadIdx.x & 31;
    if (gw >= n) return;

    float4 acc = make_float4(0.f, 0.f, 0.f, 0.f);
    const int beg = g_offs[gw];
    const int end = g_offs[gw + 1];

    int e = beg;
    for (; e + 1 < end; e += 2) {
        int2 e0 = g_edge[e];
        int2 e1 = g_edge[e + 1];
        uint2 v0 = *(const uint2*)(h + (size_t)e0.x * 128 + lane * 4);
        uint2 v1 = *(const uint2*)(h + (size_t)e1.x * 128 + lane * 4);
        fma_bf16x4(acc, v0, __int_as_float(e0.y));
        fma_bf16x4(acc, v1, __int_as_float(e1.y));
    }
    if (e < end) {
        int2 e0 = g_edge[e];
        uint2 v0 = *(const uint2*)(h + (size_t)e0.x * 128 + lane * 4);
        fma_bf16x4(acc, v0, __int_as_float(e0.y));
    }
    {
        float di = g_dinv[gw];
        uint2 v = *(const uint2*)(h + (size_t)gw * 128 + lane * 4);
        fma_bf16x4(acc, v, di * di);
    }
    float4 bv = *(const float4*)(b + lane * 4);
    acc.x = fmaxf(acc.x + bv.x, 0.f);
    acc.y = fmaxf(acc.y + bv.y, 0.f);
    acc.z = fmaxf(acc.z + bv.z, 0.f);
    acc.w = fmaxf(acc.w + bv.w, 0.f);
    uint2 o;
    *(__nv_bfloat162*)&o.x = __floats2bfloat162_rn(acc.x, acc.y);
    *(__nv_bfloat162*)&o.y = __floats2bfloat162_rn(acc.z, acc.w);
    *(uint2*)(out + (size_t)gw * 128 + lane * 4) = o;
}

// F=64 with fused log_softmax, bf16 gather in / fp32 out
__global__ void k_agg64_lsm(const __nv_bfloat16* __restrict__ h, const float* __restrict__ b,
                            float* __restrict__ out, int n) {
    int gw = (blockIdx.x * blockDim.x + threadIdx.x) >> 5;
    int lane = threadIdx.x & 31;
    if (gw >= n) return;

    float2 acc = make_float2(0.f, 0.f);
    const int beg = g_offs[gw];
    const int end = g_offs[gw + 1];

    int e = beg;
    for (; e + 1 < end; e += 2) {
        int2 e0 = g_edge[e];
        int2 e1 = g_edge[e + 1];
        uint32_t v0 = *(const uint32_t*)(h + (size_t)e0.x * 64 + lane * 2);
        uint32_t v1 = *(const uint32_t*)(h + (size_t)e1.x * 64 + lane * 2);
        float2 f0 = __bfloat1622float2(*(const __nv_bfloat162*)&v0);
        float2 f1 = __bfloat1622float2(*(const __nv_bfloat162*)&v1);
        float n0 = __int_as_float(e0.y), n1 = __int_as_float(e1.y);
        acc.x = fmaf(f0.x, n0, acc.x); acc.y = fmaf(f0.y, n0, acc.y);
        acc.x = fmaf(f1.x, n1, acc.x); acc.y = fmaf(f1.y, n1, acc.y);
    }
    if (e < end) {
        int2 e0 = g_edge[e];
        uint32_t v0 = *(const uint32_t*)(h + (size_t)e0.x * 64 + lane * 2);
        float2 f0 = __bfloat1622float2(*(const __nv_bfloat162*)&v0);
        float n0 = __int_as_float(e0.y);
        acc.x = fmaf(f0.x, n0, acc.x); acc.y = fmaf(f0.y, n0, acc.y);
    }
    {
        float di = g_dinv[gw];
        float sw = di * di;
        uint32_t v = *(const uint32_t*)(h + (size_t)gw * 64 + lane * 2);
        float2 f = __bfloat1622float2(*(const __nv_bfloat162*)&v);
        acc.x = fmaf(f.x, sw, acc.x); acc.y = fmaf(f.y, sw, acc.y);
    }
    float2 bv = *(const float2*)(b + lane * 2);
    acc.x += bv.x;
    acc.y += bv.y;

    float m = fmaxf(acc.x, acc.y);
#pragma unroll
    for (int o = 16; o > 0; o >>= 1) m = fmaxf(m, __shfl_xor_sync(0xFFFFFFFFu, m, o));
    float se = expf(acc.x - m) + expf(acc.y - m);
#pragma unroll
    for (int o = 16; o > 0; o >>= 1) se += __shfl_xor_sync(0xFFFFFFFFu, se, o);
    float ls = m + logf(se);
    *(float2*)(out + (size_t)gw * 64 + lane * 2) = make_float2(acc.x - ls, acc.y - ls);
}

// ---------------- launch ----------------
extern "C" void kernel_launch(void* const* d_in, const int* in_sizes, int n_in,
                              void* d_out, int out_size) {
    const float* x  = (const float*)d_in[0];
    const int* ei   = (const int*)d_in[1];
    const float* W0 = (const float*)d_in[2];
    const float* b0 = (const float*)d_in[3];
    const float* W1 = (const float*)d_in[4];
    const float* b1 = (const float*)d_in[5];
    const float* W2 = (const float*)d_in[6];
    const float* b2 = (const float*)d_in[7];
    float* out = (float*)d_out;

    const int N = in_sizes[0] / DIN;
    const int E = in_sizes[1] / 2;
    const int* src = ei;
    const int* dst = ei + E;

    __nv_bfloat16 *h_ptr = nullptr, *a_ptr = nullptr;
    int* deg_ptr = nullptr;
    void* st_ptr = nullptr;
    cudaGetSymbolAddress((void**)&h_ptr, g_h);
    cudaGetSymbolAddress((void**)&a_ptr, g_a);
    cudaGetSymbolAddress((void**)&deg_ptr, g_deg);
    cudaGetSymbolAddress(&st_ptr, g_state);

    const int TB = 256;
    const int nb = (N + 1023) / 1024;

    // CSR build
    cudaMemsetAsync(deg_ptr, 0, (size_t)N * sizeof(int));
    cudaMemsetAsync(st_ptr, 0, 64 * sizeof(unsigned long long));
    k_count<<<(E + TB - 1) / TB, TB>>>(dst, E);
    k_scan_all<<<nb, 256>>>(N, nb);
    k_fill<<<(E + TB - 1) / TB, TB>>>(src, dst, E);

    const int gemm_grid = (N + 63) / 64;
    const int agg_grid = (N * 32 + TB - 1) / TB;

    // layer 1: x fp32 -> h bf16 ; agg -> a bf16
    k_gemm_bf16<DIN, DH, float><<<gemm_grid, 256>>>(x, W0, h_ptr, N);
    k_agg128<<<agg_grid, TB>>>(h_ptr, b0, a_ptr, N);

    // layer 2
    k_gemm_bf16<DH, DH, __nv_bfloat16><<<gemm_grid, 256>>>(a_ptr, W1, h_ptr, N);
    k_agg128<<<agg_grid, TB>>>(h_ptr, b1, a_ptr, N);

    // layer 3 + fused log_softmax
    k_gemm_bf16<DH, DOUT, __nv_bfloat16><<<gemm_grid, 256>>>(a_ptr, W2, h_ptr, N);
    k_agg64_lsm<<<agg_grid, TB>>>(h_ptr, b2, out, N);
}